// round 17
// baseline (speedup 1.0000x reference)
#include <cuda_runtime.h>
#include <cuda_fp16.h>
#include <cstdint>

#define TT 2048
#define BB 256
#define CH 64
#define WU 32
#define NCHUNK (TT / CH)   // 32
#define RSTR 68            // smem row stride in words; 68/4=17 odd -> STS.128 conflict-free

#define LOG2E 1.4426950408889634f
#define LN2   0.6931471805599453f

// Warp-uniform max of positive floats via integer redux (f32 redux not on sm_103).
__device__ __forceinline__ float warp_max_pos(float v) {
    unsigned r;
    asm volatile("redux.sync.max.u32 %0, %1, 0xffffffff;"
                 : "=r"(r) : "r"(__float_as_uint(v)));
    return __uint_as_float(r);
}

__device__ __forceinline__ float ex2(float x) {
    float y; asm("ex2.approx.f32 %0, %1;" : "=f"(y) : "f"(x)); return y;
}
__device__ __forceinline__ float lg2(float x) {
    float y; asm("lg2.approx.f32 %0, %1;" : "=f"(y) : "f"(x)); return y;
}

// -floor(log2(m)) for positive normal m via exponent field (ALU only, exact).
__device__ __forceinline__ float neg_exp_floor(float m) {
    int e = (int)(__float_as_uint(m) >> 23) - 127;
    return (float)(-e);
}

// sign = 1 - 2*((popc(s&mask) ^ b) & 1)
__device__ __forceinline__ float sg(int s, int mask, int b) {
    return 1.0f - 2.0f * (float)((__popc(s & mask) ^ b) & 1);
}

// pack two floats to clamped half2 bits
__device__ __forceinline__ unsigned pack16(float x, float y) {
    __half2 h = __hmin2(__floats2half2_rn(x, y), __float2half2_rn(60000.0f));
    return *reinterpret_cast<unsigned*>(&h);
}
__device__ __forceinline__ float2 unpack16(unsigned u) {
    __half2 h = *reinterpret_cast<__half2*>(&u);
    return __half22float2(h);
}

struct Grp { float4 cA, cB, dd; };
__device__ __forceinline__ Grp ldgrp(const float4* ch4, const float4* la4, int tb, int g) {
    Grp r;
    const int tv = (tb + g) >> 1;
    r.cA = __ldg(ch4 + tv);
    r.cB = __ldg(ch4 + tv + 1);
    r.dd = __ldg(la4 + ((tb + g) >> 2));
    return r;
}

// ---------------------------------------------------------------------------
// One block per (batch, 64-step chunk), 2 warps.
// Warp0: alpha recursion (uniform seed WU steps early; exact delta for c=0).
// Warp1: beta recursion (uniform seed WU steps late; exact for last chunk).
// Zero-lag power-of-2 normalization (exponent extract, ALU-only) folded into
// each group's first step. Distance-1 input prefetch. Raw clamped carries
// stored via one STS.128 per group. Lane-per-t LLR with sign-group partials
// and a P,Q-only polynomial combine (common PQ scale cancels in the ratio).
// ---------------------------------------------------------------------------
__global__ __launch_bounds__(64, 1)
void bcjr_kernel(const float* __restrict__ llr_ch, const float* __restrict__ llr_a,
                 float* __restrict__ out) {
    __shared__ __align__(16) unsigned sA[32][RSTR];
    __shared__ __align__(16) unsigned sB[32][RSTR];

    const int c = blockIdx.x & (NCHUNK - 1);
    const int b = blockIdx.x >> 5;           // NCHUNK = 32
    const int tb = c * CH;
    const int w = threadIdx.x >> 5;
    const int L = threadIdx.x & 31;

    const float*  ch  = llr_ch + (size_t)b * (2 * TT);
    const float4* ch4 = (const float4*)ch;
    const float*  la  = llr_a + (size_t)b * TT;
    const float4* la4 = (const float4*)la;

    if (w == 0) {
        // ---- alpha ----
        const int bit = L >> 4;
        const int p0 = (2 * L) & 31, p1 = p0 + 1;
        const float h0 = 0.5f * LOG2E * sg(2 * p0, 57, bit);
        const float h1 = 0.5f * LOG2E * sg(2 * p0, 27, bit);
        const float hb = 0.5f * LOG2E * (1.0f - 2.0f * (float)bit);
        const float th1 = -2.0f * h1;

        float a0, a1;
        if (c == 0) { a0 = (L == 0) ? 1.0f : 0.0f; a1 = 0.0f; }
        else        { a0 = 1.0f / 64.0f; a1 = 1.0f / 64.0f; }

        Grp cur = ldgrp(ch4, la4, tb, (c == 0) ? 0 : -WU);

        // ---- warmup (no stores); prefetch rolls into main's first group ----
        if (c != 0) {
#pragma unroll 2
            for (int g = -WU; g < 0; g += 4) {
                Grp nxt = ldgrp(ch4, la4, tb, g + 4);
                float mlr = neg_exp_floor(warp_max_pos(a0 + a1));
                float l0v[4] = {cur.cA.x, cur.cA.z, cur.cB.x, cur.cB.z};
                float l1v[4] = {cur.cA.y, cur.cA.w, cur.cB.y, cur.cB.w};
                float lav[4] = {cur.dd.x, cur.dd.y, cur.dd.z, cur.dd.w};
#pragma unroll
                for (int k = 0; k < 4; k++) {
                    float z = (k == 0) ? fmaf(hb, lav[k], mlr) : hb * lav[k];
                    float a1arg = fmaf(h0, l0v[k], fmaf(h1, l1v[k], z));
                    float z2 = z + z;
                    float a2arg = z2 - a1arg;
                    float a3arg = fmaf(th1, l1v[k], a1arg);
                    float a4arg = z2 - a3arg;
                    float A1 = ex2(a1arg);
                    float A2 = ex2(a2arg);
                    float A3 = ex2(a3arg);
                    float A4 = ex2(a4arg);
                    float pa0 = __shfl_sync(0xffffffffu, a0, p0);
                    float pa1 = __shfl_sync(0xffffffffu, a1, p0);
                    float qa0 = __shfl_sync(0xffffffffu, a0, p1);
                    float qa1 = __shfl_sync(0xffffffffu, a1, p1);
                    a0 = fmaf(A2, pa1, A1 * pa0);
                    a1 = fmaf(A4, qa1, A3 * qa0);
                }
                cur = nxt;
            }
        }

        // ---- main (stores) ----
#pragma unroll 2
        for (int g = 0; g < CH; g += 4) {
            Grp nxt = ldgrp(ch4, la4, tb, (g + 4 < CH) ? g + 4 : CH - 4);
            float mlr = neg_exp_floor(warp_max_pos(a0 + a1));
            float l0v[4] = {cur.cA.x, cur.cA.z, cur.cB.x, cur.cB.z};
            float l1v[4] = {cur.cA.y, cur.cA.w, cur.cB.y, cur.cB.w};
            float lav[4] = {cur.dd.x, cur.dd.y, cur.dd.z, cur.dd.w};
            unsigned u[4];
#pragma unroll
            for (int k = 0; k < 4; k++) {
                u[k] = pack16(a0, a1);

                float z = (k == 0) ? fmaf(hb, lav[k], mlr) : hb * lav[k];
                float a1arg = fmaf(h0, l0v[k], fmaf(h1, l1v[k], z));
                float z2 = z + z;
                float a2arg = z2 - a1arg;
                float a3arg = fmaf(th1, l1v[k], a1arg);
                float a4arg = z2 - a3arg;
                float A1 = ex2(a1arg);
                float A2 = ex2(a2arg);
                float A3 = ex2(a3arg);
                float A4 = ex2(a4arg);
                float pa0 = __shfl_sync(0xffffffffu, a0, p0);
                float pa1 = __shfl_sync(0xffffffffu, a1, p0);
                float qa0 = __shfl_sync(0xffffffffu, a0, p1);
                float qa1 = __shfl_sync(0xffffffffu, a1, p1);
                a0 = fmaf(A2, pa1, A1 * pa0);
                a1 = fmaf(A4, qa1, A3 * qa0);
            }
            *reinterpret_cast<uint4*>(&sA[L][g]) = make_uint4(u[0], u[1], u[2], u[3]);
            cur = nxt;
        }
    } else {
        // ---- beta (stride-32 layout: lane L = beta[L], beta[L+32]) ----
        const float x0L = 0.5f * LOG2E * sg(L, 57, 0);
        const float x1L = 0.5f * LOG2E * sg(L, 27, 0);
        const float xbL = 0.5f * LOG2E;
        const int srcA = L >> 1;
        const int srcB = 16 + (L >> 1);

        float b0 = 1.0f / 64.0f, b1 = 1.0f / 64.0f;
        const bool haswu = (c != NCHUNK - 1);

        Grp cur = ldgrp(ch4, la4, tb, haswu ? CH + WU - 4 : CH - 4);

        // ---- warmup (no stores); prefetch rolls into main's first group ----
        if (haswu) {
#pragma unroll 2
            for (int g = CH + WU - 4; g >= CH; g -= 4) {
                Grp nxt = ldgrp(ch4, la4, tb, g - 4);
                float lr = neg_exp_floor(warp_max_pos(b0 + b1));
                float l0v[4] = {cur.cA.x, cur.cA.z, cur.cB.x, cur.cB.z};
                float l1v[4] = {cur.cA.y, cur.cA.w, cur.cB.y, cur.cB.w};
                float lav[4] = {cur.dd.x, cur.dd.y, cur.dd.z, cur.dd.w};
#pragma unroll
                for (int kk = 0; kk < 4; kk++) {
                    int k = 3 - kk;
                    float a = x0L * l0v[k];
                    float b2 = fmaf(x1L, l1v[k], xbL * lav[k]);
                    float sm = a + b2, df = a - b2;
                    float zp, zm, dp, dn;
                    if (kk == 0) { zp = sm + lr; zm = lr - sm; dp = lr + df; dn = lr - df; }
                    else         { zp = sm;      zm = -sm;      dp = df;      dn = -df;     }
                    float Z   = ex2(zp);
                    float iZ  = ex2(zm);
                    float c10 = ex2(dn);
                    float c11 = ex2(dp);
                    float s0 = __shfl_sync(0xffffffffu, b0, srcA);
                    float s1 = __shfl_sync(0xffffffffu, b1, srcA);
                    float t0s = __shfl_sync(0xffffffffu, b0, srcB);
                    float t1s = __shfl_sync(0xffffffffu, b1, srcB);
                    b0 = fmaf(iZ, s1, Z * s0);
                    b1 = fmaf(c11, t1s, c10 * t0s);
                }
                cur = nxt;
            }
        }

        // ---- main (stores) ----
#pragma unroll 2
        for (int g = CH - 4; g >= 0; g -= 4) {
            Grp nxt = ldgrp(ch4, la4, tb, (g >= 4) ? g - 4 : 0);
            float lr = neg_exp_floor(warp_max_pos(b0 + b1));
            float l0v[4] = {cur.cA.x, cur.cA.z, cur.cB.x, cur.cB.z};
            float l1v[4] = {cur.cA.y, cur.cA.w, cur.cB.y, cur.cB.w};
            float lav[4] = {cur.dd.x, cur.dd.y, cur.dd.z, cur.dd.w};
            unsigned u[4];
#pragma unroll
            for (int kk = 0; kk < 4; kk++) {
                int k = 3 - kk;
                u[k] = pack16(b0, b1);   // carry = beta_{t+1} at slot t = g + k

                float a = x0L * l0v[k];
                float b2 = fmaf(x1L, l1v[k], xbL * lav[k]);
                float sm = a + b2, df = a - b2;
                float zp, zm, dp, dn;
                if (kk == 0) { zp = sm + lr; zm = lr - sm; dp = lr + df; dn = lr - df; }
                else         { zp = sm;      zm = -sm;      dp = df;      dn = -df;     }
                float Z   = ex2(zp);
                float iZ  = ex2(zm);
                float c10 = ex2(dn);
                float c11 = ex2(dp);
                float s0 = __shfl_sync(0xffffffffu, b0, srcA);
                float s1 = __shfl_sync(0xffffffffu, b1, srcA);
                float t0s = __shfl_sync(0xffffffffu, b0, srcB);
                float t1s = __shfl_sync(0xffffffffu, b1, srcB);
                b0 = fmaf(iZ, s1, Z * s0);
                b1 = fmaf(c11, t1s, c10 * t0s);
            }
            *reinterpret_cast<uint4*>(&sB[L][g]) = make_uint4(u[0], u[1], u[2], u[3]);
            cur = nxt;
        }
    }

    __syncthreads();

    // ---- LLR: lane-per-t, sign-group partials; P,Q-only polynomial combine ----
    {
        int tl = w * 32 + L;
        int t = tb + tl;
        float2 l01 = __ldg((const float2*)ch + t);
        float l0 = l01.x, l1 = l01.y;
        float laa = __ldg(la + t);

        float sp = 0.5f * LOG2E * (l0 + l1);
        float dm = 0.5f * LOG2E * (l0 - l1);
        float P = ex2(sp);
        float Q = ex2(dm);

        float T0[4] = {0, 0, 0, 0};
        float T1[4] = {0, 0, 0, 0};
        float U0[4] = {0, 0, 0, 0};
        float U1[4] = {0, 0, 0, 0};
#pragma unroll
        for (int s = 0; s < 32; s++) {
            const int par0 = (__popc(s & 28)) & 1;
            const int par1 = (__popc(s & 13)) & 1;
            const int gI = par0 * 2 + par1;

            float2 a  = unpack16(sA[s][tl]);
            float2 bb = unpack16(sB[s][tl]);
            T0[gI] = fmaf(bb.x, a.x, T0[gI]);
            T1[gI] = fmaf(bb.x, a.y, T1[gI]);
            U0[gI] = fmaf(bb.y, a.x, U0[gI]);
            U1[gI] = fmaf(bb.y, a.y, U1[gI]);
        }
        // group: 0 -> X=P, 1 -> X=Q, 2 -> X=iQ, 3 -> X=iP; scale both sums by PQ:
        // S*PQ = A*P2Q + B*Q + C*PQ2 + D*P   (PQ cancels in the log-ratio)
        float A  = T0[0] + T1[3], B  = T1[0] + T0[3];
        float C  = T0[1] + T1[2], D  = T1[1] + T0[2];
        float A2 = U1[0] + U0[3], B2 = U0[0] + U1[3];
        float C2 = U1[1] + U0[2], D2 = U0[1] + U1[2];

        float PQ  = P * Q;
        float P2Q = PQ * P;
        float PQ2 = PQ * Q;
        float S0 = fmaf(A,  P2Q, fmaf(C,  PQ2, fmaf(D,  P, B  * Q)));
        float S1 = fmaf(A2, P2Q, fmaf(C2, PQ2, fmaf(D2, P, B2 * Q)));

        out[(size_t)b * TT + t] = fmaf(LN2, lg2(S0) - lg2(S1), laa);
    }
}

extern "C" void kernel_launch(void* const* d_in, const int* in_sizes, int n_in,
                              void* d_out, int out_size) {
    const float* llr_ch = (const float*)d_in[0];   // [256, 4096]
    const float* llr_a  = (const float*)d_in[1];   // [256, 2048]
    float* out = (float*)d_out;                    // [256, 2048]

    bcjr_kernel<<<BB * NCHUNK, 64>>>(llr_ch, llr_a, out);
}